// round 3
// baseline (speedup 1.0000x reference)
#include <cuda_runtime.h>
#include <cuda_bf16.h>

// Shapes (fixed by the problem)
#define BB   8
#define NN   16384
#define SS   1024
#define TT   2
#define TPB  256
#define NPT  4

// Scratch (no cudaMalloc allowed): per-(batch,s) min-over-n as float bits,
// chamfer1 uses [0,8192), chamfer2 uses [8192, 24576).
__device__ unsigned int g_smin[24576];
// [0]=sum of n-side mins chamfer1, [1]=chamfer2, [2]=consistency sq-sum
__device__ double g_acc[4];

__device__ __forceinline__ float block_reduce_sum(float v, float* sh) {
    #pragma unroll
    for (int o = 16; o > 0; o >>= 1) v += __shfl_down_sync(0xffffffffu, v, o);
    int lane = threadIdx.x & 31, w = threadIdx.x >> 5;
    if (lane == 0) sh[w] = v;
    __syncthreads();
    float r = 0.f;
    if (w == 0) {
        int nw = blockDim.x >> 5;
        r = (lane < nw) ? sh[lane] : 0.f;
        #pragma unroll
        for (int o = 16; o > 0; o >>= 1) r += __shfl_down_sync(0xffffffffu, r, o);
    }
    return r; // valid in thread 0
}

__global__ void k_reset() {
    int i = blockIdx.x * blockDim.x + threadIdx.x;
    if (i < 24576) g_smin[i] = 0x7f800000u; // +inf
    if (i < 4) g_acc[i] = 0.0;
}

// For each point x in X (n_per_batch per batch), min squared dist over the
// 1024 Y points of the same batch; accumulate sum of mins into g_acc[acc_idx].
__global__ void k_nside(const float* __restrict__ X, const float* __restrict__ Y,
                        int n_per_batch, int acc_idx) {
    __shared__ float4 ys[SS];
    __shared__ float red[32];
    int b = blockIdx.y;
    const float* Yb = Y + (size_t)b * SS * 3;
    for (int i = threadIdx.x; i < SS; i += TPB)
        ys[i] = make_float4(Yb[3*i], Yb[3*i+1], Yb[3*i+2], 0.f);
    __syncthreads();

    const float* Xb = X + (size_t)b * n_per_batch * 3;
    int n0 = blockIdx.x * (TPB * NPT) + threadIdx.x;
    float x0[NPT], x1[NPT], x2[NPT], mn[NPT];
    #pragma unroll
    for (int k = 0; k < NPT; k++) {
        int n = n0 + k * TPB;
        x0[k] = Xb[3*n]; x1[k] = Xb[3*n+1]; x2[k] = Xb[3*n+2];
        mn[k] = 3.4e38f;
    }
    for (int s = 0; s < SS; s++) {
        float4 y = ys[s];
        #pragma unroll
        for (int k = 0; k < NPT; k++) {
            float dx = x0[k] - y.x, dy = x1[k] - y.y, dz = x2[k] - y.z;
            float d = fmaf(dz, dz, fmaf(dy, dy, dx * dx));
            mn[k] = fminf(mn[k], d);
        }
    }
    float s4 = (mn[0] + mn[1]) + (mn[2] + mn[3]);
    float bs = block_reduce_sum(s4, red);
    if (threadIdx.x == 0) atomicAdd(&g_acc[acc_idx], (double)bs);
}

// For each structure point s (1024 per batch), min over a 1024-point chunk of
// X (gt); finish with global atomicMin on float bits (dists >= 0).
__global__ void k_sside(const float* __restrict__ X, const float* __restrict__ Y,
                        int n_per_batch, int smin_off) {
    __shared__ float4 xs[1024];
    int b = blockIdx.y;
    const float* Xb = X + (size_t)b * n_per_batch * 3 + (size_t)blockIdx.x * 1024 * 3;
    for (int i = threadIdx.x; i < 1024; i += TPB)
        xs[i] = make_float4(Xb[3*i], Xb[3*i+1], Xb[3*i+2], 0.f);
    __syncthreads();

    const float* Yb = Y + (size_t)b * SS * 3;
    float y0[NPT], y1[NPT], y2[NPT], mn[NPT];
    #pragma unroll
    for (int k = 0; k < NPT; k++) {
        int s = threadIdx.x + k * TPB;
        y0[k] = Yb[3*s]; y1[k] = Yb[3*s+1]; y2[k] = Yb[3*s+2];
        mn[k] = 3.4e38f;
    }
    for (int i = 0; i < 1024; i++) {
        float4 x = xs[i];
        #pragma unroll
        for (int k = 0; k < NPT; k++) {
            float dx = y0[k] - x.x, dy = y1[k] - x.y, dz = y2[k] - x.z;
            float d = fmaf(dz, dz, fmaf(dy, dy, dx * dx));
            mn[k] = fminf(mn[k], d);
        }
    }
    #pragma unroll
    for (int k = 0; k < NPT; k++) {
        int s = threadIdx.x + k * TPB;
        atomicMin(&g_smin[smin_off + b * SS + s], __float_as_uint(mn[k]));
    }
}

// tmp[t,b,s,e] = sum_d structure[b,s,d]*trans[t,d,e]; acc += (tmp - tsp)^2
__global__ void k_consist(const float* __restrict__ sp, const float* __restrict__ tsp,
                          const float* __restrict__ tm) {
    __shared__ float red[32];
    int i = blockIdx.x * blockDim.x + threadIdx.x;  // 0 .. T*B*S-1 = 16383
    int t = i >> 13;            // / (B*S)
    int rem = i & 8191;         // b*S + s
    const float* p = sp + 3 * rem;
    float a = p[0], bq = p[1], c = p[2];
    const float* M = tm + 9 * t;
    float acc = 0.f;
    #pragma unroll
    for (int e = 0; e < 3; e++) {
        float v = fmaf(a, M[e], fmaf(bq, M[3 + e], c * M[6 + e]));
        float diff = v - tsp[(size_t)i * 3 + e];
        acc = fmaf(diff, diff, acc);
    }
    float bsum = block_reduce_sum(acc, red);
    if (threadIdx.x == 0) atomicAdd(&g_acc[2], (double)bsum);
}

__global__ void k_final(float* __restrict__ out) {
    __shared__ double sh1[32], sh2[32];
    double s1 = 0.0, s2 = 0.0;
    for (int i = threadIdx.x; i < 8192; i += blockDim.x)
        s1 += (double)__uint_as_float(g_smin[i]);
    for (int i = 8192 + threadIdx.x; i < 24576; i += blockDim.x)
        s2 += (double)__uint_as_float(g_smin[i]);
    #pragma unroll
    for (int o = 16; o > 0; o >>= 1) {
        s1 += __shfl_down_sync(0xffffffffu, s1, o);
        s2 += __shfl_down_sync(0xffffffffu, s2, o);
    }
    int lane = threadIdx.x & 31, w = threadIdx.x >> 5;
    if (lane == 0) { sh1[w] = s1; sh2[w] = s2; }
    __syncthreads();
    if (threadIdx.x == 0) {
        int nw = blockDim.x >> 5;
        double t1 = 0.0, t2 = 0.0;
        for (int j = 0; j < nw; j++) { t1 += sh1[j]; t2 += sh2[j]; }
        double mean_s1 = t1 / (double)(BB * SS);                 // 8192
        double mean_n1 = g_acc[0] / (double)(BB * NN);           // 131072
        double c1 = 0.5 * (mean_s1 + mean_n1);
        double mean_s2 = t2 / (double)(TT * BB * SS);            // 16384
        double mean_n2 = g_acc[1] / (double)(TT * BB * NN);      // 262144
        double c2 = 0.5 * (mean_s2 + mean_n2);
        double cd = (c1 + c2) / (double)(TT + 1);
        double mse = g_acc[2] / (double)(TT * BB * SS * 3) * 1000.0;
        out[0] = (float)(cd + mse);
    }
}

extern "C" void kernel_launch(void* const* d_in, const int* in_sizes, int n_in,
                              void* d_out, int out_size) {
    const float* gt  = (const float*)d_in[0];  // [B,N,3]
    const float* sp  = (const float*)d_in[1];  // [B,S,3]
    const float* tgt = (const float*)d_in[2];  // [T,B,N,3] -> [16,N,3]
    const float* tsp = (const float*)d_in[3];  // [T,B,S,3] -> [16,S,3]
    const float* tm  = (const float*)d_in[4];  // [T,3,3]
    float* out = (float*)d_out;

    k_reset<<<96, TPB>>>();

    dim3 g1(NN / (TPB * NPT), BB);        // (16, 8)
    dim3 g2(NN / (TPB * NPT), TT * BB);   // (16, 16)
    k_nside<<<g1, TPB>>>(gt,  sp,  NN, 0);
    k_nside<<<g2, TPB>>>(tgt, tsp, NN, 1);
    k_sside<<<g1, TPB>>>(gt,  sp,  NN, 0);
    k_sside<<<g2, TPB>>>(tgt, tsp, NN, 8192);

    k_consist<<<(TT * BB * SS) / TPB, TPB>>>(sp, tsp, tm);
    k_final<<<1, 1024>>>(out);
}

// round 7
// speedup vs baseline: 1.5904x; 1.5904x over previous
#include <cuda_runtime.h>
#include <cuda_bf16.h>

// Shapes (fixed)
#define BB   8
#define NN   16384
#define SS   1024
#define TT   2
#define TPB  256
#define NPT  4

// Scratch: per-(batch,s) min-over-n as order-preserving uint keys.
// chamfer1 uses [0,8192), chamfer2 uses [8192, 24576).
__device__ unsigned int g_smin[24576];
// [0]=sum of n-side mins chamfer1, [1]=chamfer2, [2]=consistency sq-sum
__device__ double g_acc[4];

// order-preserving float -> uint (works for negatives)
__device__ __forceinline__ unsigned int f2key(float f) {
    unsigned int u = __float_as_uint(f);
    return u ^ ((unsigned int)((int)u >> 31) | 0x80000000u);
}
__device__ __forceinline__ float key2f(unsigned int k) {
    unsigned int u = (k & 0x80000000u) ? (k ^ 0x80000000u) : ~k;
    return __uint_as_float(u);
}

__device__ __forceinline__ float block_reduce_sum(float v, float* sh) {
    #pragma unroll
    for (int o = 16; o > 0; o >>= 1) v += __shfl_down_sync(0xffffffffu, v, o);
    int lane = threadIdx.x & 31, w = threadIdx.x >> 5;
    if (lane == 0) sh[w] = v;
    __syncthreads();
    float r = 0.f;
    if (w == 0) {
        r = (lane < (int)(blockDim.x >> 5)) ? sh[lane] : 0.f;
        #pragma unroll
        for (int o = 16; o > 0; o >>= 1) r += __shfl_down_sync(0xffffffffu, r, o);
    }
    return r; // valid in thread 0
}

__global__ void k_reset() {
    int i = blockIdx.x * blockDim.x + threadIdx.x;
    if (i < 24576) g_smin[i] = 0xffffffffu;   // max key
    if (i < 4) g_acc[i] = 0.0;
}

// One fused kernel: 832 blocks.
//  [0,128)   role A: n-side chamfer1  (gt vs sp)          -> g_acc[0]
//  [128,384) role B: n-side chamfer2  (tgt vs tsp)        -> g_acc[1]
//  [384,512) role C: s-side chamfer1  (sp vs gt chunk)    -> g_smin[0..8192)
//  [512,768) role D: s-side chamfer2  (tsp vs tgt chunk)  -> g_smin[8192..)
//  [768,832) role E: consistency MSE                      -> g_acc[2]
__global__ void k_fused(const float* __restrict__ gt, const float* __restrict__ sp,
                        const float* __restrict__ tgt, const float* __restrict__ tsp,
                        const float* __restrict__ tm) {
    __shared__ float4 ypts[1024];
    __shared__ float red[32];
    int blk = blockIdx.x;
    int tid = threadIdx.x;

    if (blk >= 768) {
        // ---- consistency term ----
        int i = (blk - 768) * TPB + tid;      // 0..16383
        int t = i >> 13;
        int rem = i & 8191;
        const float* p = sp + 3 * rem;
        float a = p[0], b = p[1], c = p[2];
        const float* M = tm + 9 * t;
        float acc = 0.f;
        #pragma unroll
        for (int e = 0; e < 3; e++) {
            float v = fmaf(a, M[e], fmaf(b, M[3 + e], c * M[6 + e]));
            float diff = v - tsp[(size_t)i * 3 + e];
            acc = fmaf(diff, diff, acc);
        }
        float bsum = block_reduce_sum(acc, red);
        if (tid == 0) atomicAdd(&g_acc[2], (double)bsum);
        return;
    }

    // ---- chamfer roles ----
    const float* smem_src;   // 1024 points loaded to smem as (-2p, |p|^2)
    const float* thr_src;    // 1024 points held in registers (NPT per thread)
    bool nside;
    int target;              // acc index (nside) or g_smin offset (sside)

    if (blk < 128) {                       // A
        int b = blk >> 4, chunk = blk & 15;
        smem_src = sp + (size_t)b * SS * 3;
        thr_src  = gt + (size_t)b * NN * 3 + (size_t)chunk * 1024 * 3;
        nside = true; target = 0;
    } else if (blk < 384) {                // B
        int idx = blk - 128, tb = idx >> 4, chunk = idx & 15;
        smem_src = tsp + (size_t)tb * SS * 3;
        thr_src  = tgt + (size_t)tb * NN * 3 + (size_t)chunk * 1024 * 3;
        nside = true; target = 1;
    } else if (blk < 512) {                // C
        int idx = blk - 384, b = idx >> 4, chunk = idx & 15;
        smem_src = gt + (size_t)b * NN * 3 + (size_t)chunk * 1024 * 3;
        thr_src  = sp + (size_t)b * SS * 3;
        nside = false; target = b * SS;
    } else {                               // D
        int idx = blk - 512, tb = idx >> 4, chunk = idx & 15;
        smem_src = tgt + (size_t)tb * NN * 3 + (size_t)chunk * 1024 * 3;
        thr_src  = tsp + (size_t)tb * SS * 3;
        nside = false; target = 8192 + tb * SS;
    }

    // load shared tile: (-2x, -2y, -2z, x^2+y^2+z^2)
    for (int i = tid; i < 1024; i += TPB) {
        const float* p = smem_src + 3 * i;
        float a = p[0], b = p[1], c = p[2];
        float sq = fmaf(a, a, fmaf(b, b, c * c));
        ypts[i] = make_float4(-2.f * a, -2.f * b, -2.f * c, sq);
    }
    __syncthreads();

    // thread-private points + their squared norms
    float x0[NPT], x1[NPT], x2[NPT], sq[NPT], mn[NPT];
    #pragma unroll
    for (int k = 0; k < NPT; k++) {
        const float* p = thr_src + 3 * (tid + k * TPB);
        x0[k] = p[0]; x1[k] = p[1]; x2[k] = p[2];
        sq[k] = fmaf(x0[k], x0[k], fmaf(x1[k], x1[k], x2[k] * x2[k]));
        mn[k] = 3.4e38f;
    }

    // core loop: 4 issue slots per pair (3 FFMA + 1 FMNMX)
    #pragma unroll 4
    for (int s = 0; s < 1024; s++) {
        float4 y = ypts[s];
        #pragma unroll
        for (int k = 0; k < NPT; k++) {
            float v = fmaf(y.x, x0[k], y.w);
            v = fmaf(y.y, x1[k], v);
            v = fmaf(y.z, x2[k], v);
            mn[k] = fminf(mn[k], v);
        }
    }

    if (nside) {
        float s4 = 0.f;
        #pragma unroll
        for (int k = 0; k < NPT; k++) s4 += mn[k] + sq[k];
        float bs = block_reduce_sum(s4, red);
        if (tid == 0) atomicAdd(&g_acc[target], (double)bs);
    } else {
        #pragma unroll
        for (int k = 0; k < NPT; k++)
            atomicMin(&g_smin[target + tid + k * TPB], f2key(mn[k] + sq[k]));
    }
}

__global__ void k_final(float* __restrict__ out) {
    __shared__ double sh1[32], sh2[32];
    double s1 = 0.0, s2 = 0.0;
    for (int i = threadIdx.x; i < 8192; i += blockDim.x)
        s1 += (double)key2f(g_smin[i]);
    for (int i = 8192 + threadIdx.x; i < 24576; i += blockDim.x)
        s2 += (double)key2f(g_smin[i]);
    #pragma unroll
    for (int o = 16; o > 0; o >>= 1) {
        s1 += __shfl_down_sync(0xffffffffu, s1, o);
        s2 += __shfl_down_sync(0xffffffffu, s2, o);
    }
    int lane = threadIdx.x & 31, w = threadIdx.x >> 5;
    if (lane == 0) { sh1[w] = s1; sh2[w] = s2; }
    __syncthreads();
    if (threadIdx.x == 0) {
        int nw = blockDim.x >> 5;
        double t1 = 0.0, t2 = 0.0;
        for (int j = 0; j < nw; j++) { t1 += sh1[j]; t2 += sh2[j]; }
        double mean_s1 = t1 / (double)(BB * SS);
        double mean_n1 = g_acc[0] / (double)(BB * NN);
        double c1 = 0.5 * (mean_s1 + mean_n1);
        double mean_s2 = t2 / (double)(TT * BB * SS);
        double mean_n2 = g_acc[1] / (double)(TT * BB * NN);
        double c2 = 0.5 * (mean_s2 + mean_n2);
        double cd = (c1 + c2) / (double)(TT + 1);
        double mse = g_acc[2] / (double)(TT * BB * SS * 3) * 1000.0;
        out[0] = (float)(cd + mse);
    }
}

extern "C" void kernel_launch(void* const* d_in, const int* in_sizes, int n_in,
                              void* d_out, int out_size) {
    const float* gt  = (const float*)d_in[0];  // [B,N,3]
    const float* sp  = (const float*)d_in[1];  // [B,S,3]
    const float* tgt = (const float*)d_in[2];  // [T,B,N,3]
    const float* tsp = (const float*)d_in[3];  // [T,B,S,3]
    const float* tm  = (const float*)d_in[4];  // [T,3,3]
    float* out = (float*)d_out;

    k_reset<<<96, TPB>>>();
    k_fused<<<832, TPB>>>(gt, sp, tgt, tsp, tm);
    k_final<<<1, 1024>>>(out);
}